// round 14
// baseline (speedup 1.0000x reference)
#include <cuda_runtime.h>
#include <cuda_bf16.h>
#include <cuda_fp16.h>
#include <cuda_fp8.h>
#include <cstdint>

// Problem constants
#define Bq 32
#define Dd 512
#define Tt 256
#define Nq 8192
#define Kc 8192

// GEMM tiling (fp8: BK=64 -> 64B rows)
#define BM 128
#define BN 256
#define BK 64
#define STAGES 4
#define STG_A (BM * BK)              // 8192 B
#define STG_B (BN * BK)              // 16384 B
#define STG_BYTES (STG_A + STG_B)    // 24576 B
#define KITERS (Dd / BK)             // 8
#define NTHREADS 512

#define EMIT_M    40.0f   // block-local emission margin (> 2*eps_fp8max)
#define RESCORE_M 32.0f   // exact-rescore margin (>= 2*eps_fp8max)
#define MAXC      512     // per-query candidate cap

// Scratch (device globals)
__device__ unsigned char g_A8[(size_t)Nq * Dd];   // queries e4m3 [n][d]
__device__ float         g_At[(size_t)Nq * Dd];   // queries fp32 [n][d]
__device__ unsigned char g_B8[(size_t)Kc * Dd];   // codebook e4m3 [c][d]
__device__ uint2         g_cand[(size_t)Nq * MAXC]; // (dist fp32, code)
__device__ int           g_qcnt[Nq];
__device__ float         g_c2[Kc];
__device__ int           g_cnt[Kc];
__device__ float         g_loss;

// ---------------------------------------------------------------------------
// helpers
// ---------------------------------------------------------------------------
__device__ __forceinline__ uint32_t smem_u32(const void* p) {
    uint32_t a;
    asm("{ .reg .u64 t; cvta.to.shared.u64 t, %1; cvt.u32.u64 %0, t; }" : "=r"(a) : "l"(p));
    return a;
}
__device__ __forceinline__ void cp_async16(uint32_t s, const void* g) {
    asm volatile("cp.async.cg.shared.global [%0], [%1], 16;" :: "r"(s), "l"(g) : "memory");
}
#define CP_COMMIT() asm volatile("cp.async.commit_group;" ::: "memory")
#define CP_WAIT2()  asm volatile("cp.async.wait_group 2;" ::: "memory")
#define CP_WAIT0()  asm volatile("cp.async.wait_group 0;" ::: "memory")
#define SWZ(o) ((o) ^ (((o) >> 3) & 0x70))

__device__ __forceinline__ void ldm_x4(uint32_t& r0, uint32_t& r1, uint32_t& r2, uint32_t& r3,
                                       uint32_t a) {
    asm volatile("ldmatrix.sync.aligned.m8n8.x4.shared.b16 {%0,%1,%2,%3}, [%4];"
                 : "=r"(r0), "=r"(r1), "=r"(r2), "=r"(r3) : "r"(a));
}
__device__ __forceinline__ void mma_fp8(float* c, const uint32_t* a, const uint32_t* b) {
    asm volatile(
        "mma.sync.aligned.m16n8k32.row.col.f32.e4m3.e4m3.f32 "
        "{%0,%1,%2,%3}, {%4,%5,%6,%7}, {%8,%9}, {%0,%1,%2,%3};"
        : "+f"(c[0]), "+f"(c[1]), "+f"(c[2]), "+f"(c[3])
        : "r"(a[0]), "r"(a[1]), "r"(a[2]), "r"(a[3]), "r"(b[0]), "r"(b[1]));
}
__device__ __forceinline__ unsigned f_ord(float f) {
    unsigned u = __float_as_uint(f);
    return (u & 0x80000000u) ? ~u : (u | 0x80000000u);
}
__device__ __forceinline__ uint32_t fp8x4(float a, float b, float c, float d) {
    uint32_t lo = __nv_cvt_float2_to_fp8x2(make_float2(a, b), __NV_SATFINITE, __NV_E4M3);
    uint32_t hi = __nv_cvt_float2_to_fp8x2(make_float2(c, d), __NV_SATFINITE, __NV_E4M3);
    return lo | (hi << 16);
}

// ---------------------------------------------------------------------------
// 1: fused conversions. blocks [0,512): A transpose+convert; [512,4608): B.
// ---------------------------------------------------------------------------
__global__ __launch_bounds__(256) void k_conv(const float* __restrict__ z,
                                              const float* __restrict__ cb) {
    __shared__ float shbuf[32 * 257];
    int t = threadIdx.x;
    if (blockIdx.x < 512) {
        // --- A: transpose z (b,d,t) -> [n][d] fp32 + e4m3
        int b = blockIdx.x >> 4, d0 = (blockIdx.x & 15) * 32;
        float (*sm)[257] = (float(*)[257])shbuf;
        const float* zb = z + ((size_t)b * Dd + d0) * Tt;
#pragma unroll
        for (int r = 0; r < 32; r++) sm[r][t] = zb[r * Tt + t];
        __syncthreads();
        size_t row = (size_t)(b * Tt + t) * Dd + d0;
        float* pf = g_At + row;
        float v[32];
#pragma unroll
        for (int r = 0; r < 32; r++) { v[r] = sm[r][t]; pf[r] = v[r]; }
        uint32_t w[8];
#pragma unroll
        for (int q = 0; q < 8; q++)
            w[q] = fp8x4(v[4 * q], v[4 * q + 1], v[4 * q + 2], v[4 * q + 3]);
        uint4* p8 = (uint4*)(g_A8 + row);
        p8[0] = make_uint4(w[0], w[1], w[2], w[3]);
        p8[1] = make_uint4(w[4], w[5], w[6], w[7]);
    } else {
        // --- B: codebook -> e4m3 + exact fp32 norms (2 codes per block)
        int cid0 = (int)(blockIdx.x - 512) * 2;
        int code = cid0 + (t >> 7);
        int tl = t & 127;
        float4 v = *(const float4*)(cb + (size_t)code * Dd + 4 * tl);
        *(uint32_t*)(g_B8 + (size_t)code * Dd + 4 * tl) = fp8x4(v.x, v.y, v.z, v.w);
        float s = v.x * v.x + v.y * v.y + v.z * v.z + v.w * v.w;
#pragma unroll
        for (int off = 16; off; off >>= 1) s += __shfl_down_sync(0xFFFFFFFFu, s, off);
        float* ws = shbuf;
        if ((t & 31) == 0) ws[t >> 5] = s;
        __syncthreads();
        if (t == 0)   g_c2[cid0]     = ws[0] + ws[1] + ws[2] + ws[3];
        if (t == 128) g_c2[cid0 + 1] = ws[4] + ws[5] + ws[6] + ws[7];
    }
}

// 2,3: zero kernels (also position k_gemm as launch #4 for ncu)
__global__ void k_zero1() {
    int i = blockIdx.x * 256 + threadIdx.x;
    g_qcnt[i] = 0;
}
__global__ void k_zero2() {
    int i = blockIdx.x * 256 + threadIdx.x;
    g_cnt[i] = 0;
    if (i == 0) g_loss = 0.0f;
}

// ---------------------------------------------------------------------------
// 4: e4m3 MMA GEMM 128x256x64, 16 warps (warp tile 32x64), 4-stage cp.async.
//    Epilogue: per-row local min + margin -> emit (dist,code) candidates.
//    grid (64, 32), block 512, dyn smem 96KB
// ---------------------------------------------------------------------------
__global__ __launch_bounds__(NTHREADS, 1) void k_gemm() {
    extern __shared__ char smem[];
    const uint32_t sbase = smem_u32(smem);
    const int tid = threadIdx.x;
    const int wid = tid >> 5, lane = tid & 31;
    const int wm = (wid & 3) * 32;        // warp m offset
    const int wn = (wid >> 2) * 64;       // warp n offset
    const int m0 = blockIdx.x * BM, n0 = blockIdx.y * BN;

    const unsigned char* gA = g_A8;
    const unsigned char* gB = g_B8;

    float acc[2][8][4];
#pragma unroll
    for (int i = 0; i < 2; i++)
#pragma unroll
        for (int j = 0; j < 8; j++)
#pragma unroll
            for (int k = 0; k < 4; k++) acc[i][j][k] = 0.0f;

    auto load_stage = [&](int s, int kb) {
        uint32_t sA = sbase + s * STG_BYTES;
        uint32_t sB = sA + STG_A;
        {
            int r = tid >> 2, c = tid & 3;
            uint32_t off = r * 64 + c * 16;
            cp_async16(sA + SWZ(off), gA + (size_t)(m0 + r) * Dd + kb + c * 16);
        }
#pragma unroll
        for (int p = 0; p < 2; p++) {
            int j = tid + NTHREADS * p;
            int r = j >> 2, c = j & 3;
            uint32_t off = r * 64 + c * 16;
            cp_async16(sB + SWZ(off), gB + (size_t)(n0 + r) * Dd + kb + c * 16);
        }
    };

    load_stage(0, 0); CP_COMMIT();
    load_stage(1, BK); CP_COMMIT();
    load_stage(2, 2 * BK); CP_COMMIT();

    for (int i = 0; i < KITERS; i++) {
        CP_WAIT2();
        __syncthreads();
        int s = i & 3;
        if (i + 3 < KITERS) load_stage((i + 3) & 3, (i + 3) * BK);
        CP_COMMIT();

        uint32_t sA = sbase + s * STG_BYTES;
        uint32_t sB = sA + STG_A;
#pragma unroll
        for (int k32 = 0; k32 < 2; k32++) {
            const int ch = 2 * k32 + (lane >> 4);
            uint32_t af[2][4], br[4][4];
#pragma unroll
            for (int mf = 0; mf < 2; mf++) {
                int r = wm + mf * 16 + (lane & 15);
                uint32_t off = r * 64 + ch * 16;
                ldm_x4(af[mf][0], af[mf][1], af[mf][2], af[mf][3], sA + SWZ(off));
            }
#pragma unroll
            for (int nf4 = 0; nf4 < 4; nf4++) {
                int r = wn + nf4 * 16 + (lane & 15);
                uint32_t off = r * 64 + ch * 16;
                ldm_x4(br[nf4][0], br[nf4][1], br[nf4][2], br[nf4][3], sB + SWZ(off));
            }
#pragma unroll
            for (int mf = 0; mf < 2; mf++)
#pragma unroll
                for (int nf4 = 0; nf4 < 4; nf4++) {
                    uint32_t b0[2] = {br[nf4][0], br[nf4][2]};
                    uint32_t b1[2] = {br[nf4][1], br[nf4][3]};
                    mma_fp8(acc[mf][2 * nf4],     af[mf], b0);
                    mma_fp8(acc[mf][2 * nf4 + 1], af[mf], b1);
                }
        }
    }

    // --- epilogue: acc -> dist; per-row (local) min; emit d < localmin+M
    CP_WAIT0();
    __syncthreads();                       // smem reusable
    float (*srm)[4] = (float(*)[4])smem;   // [128][4] row-min per n-warp-group

    // distances in place: d = c2 - 2*dot
#pragma unroll
    for (int nf = 0; nf < 8; nf++) {
        int n = n0 + wn + nf * 8 + (lane & 3) * 2;
        float c2a = g_c2[n], c2b = g_c2[n + 1];
#pragma unroll
        for (int mf = 0; mf < 2; mf++) {
            acc[mf][nf][0] = c2a - 2.0f * acc[mf][nf][0];
            acc[mf][nf][1] = c2b - 2.0f * acc[mf][nf][1];
            acc[mf][nf][2] = c2a - 2.0f * acc[mf][nf][2];
            acc[mf][nf][3] = c2b - 2.0f * acc[mf][nf][3];
        }
    }

    // per-thread row mins, then across the 4 lanes sharing a row
    float rmv[2][2];
#pragma unroll
    for (int mf = 0; mf < 2; mf++)
#pragma unroll
        for (int h = 0; h < 2; h++) {
            float m = 3.4e38f;
#pragma unroll
            for (int nf = 0; nf < 8; nf++)
                m = fminf(m, fminf(acc[mf][nf][2 * h], acc[mf][nf][2 * h + 1]));
            m = fminf(m, __shfl_xor_sync(0xFFFFFFFFu, m, 1));
            m = fminf(m, __shfl_xor_sync(0xFFFFFFFFu, m, 2));
            rmv[mf][h] = m;
        }
    if ((lane & 3) == 0) {
#pragma unroll
        for (int mf = 0; mf < 2; mf++)
#pragma unroll
            for (int h = 0; h < 2; h++)
                srm[wm + mf * 16 + (lane >> 2) + 8 * h][wid >> 2] = rmv[mf][h];
    }
    __syncthreads();

#pragma unroll
    for (int mf = 0; mf < 2; mf++) {
#pragma unroll
        for (int h = 0; h < 2; h++) {
            int r = wm + mf * 16 + (lane >> 2) + 8 * h;
            float* s4 = srm[r];
            float th = fminf(fminf(s4[0], s4[1]), fminf(s4[2], s4[3])) + EMIT_M;
#pragma unroll
            for (int nf = 0; nf < 8; nf++) {
#pragma unroll
                for (int k = 0; k < 2; k++) {
                    float dv = acc[mf][nf][2 * h + k];
                    if (dv < th) {
                        int code = n0 + wn + nf * 8 + (lane & 3) * 2 + k;
                        int pos = atomicAdd(&g_qcnt[m0 + r], 1);
                        if (pos < MAXC)
                            g_cand[(size_t)(m0 + r) * MAXC + pos] =
                                make_uint2(__float_as_uint(dv), (unsigned)code);
                    }
                }
            }
        }
    }
}

// ---------------------------------------------------------------------------
// 5: fused select + rescore + gather + loss. warp per query; 8 queries/block.
//    grid 1024, block 256
// ---------------------------------------------------------------------------
__global__ __launch_bounds__(256) void k_scanout(const float* __restrict__ z,
                                                 const float* __restrict__ cb,
                                                 float* __restrict__ out) {
    __shared__ float st[512][9];
    __shared__ float wls[8];
    const int tid = threadIdx.x;
    const int wid = tid >> 5, lane = tid & 31;
    const int q = blockIdx.x * 8 + wid;

    int cnt = min(g_qcnt[q], MAXC);
    const uint2* lst = g_cand + (size_t)q * MAXC;

    // approx global min over the candidate list
    float gmin = 3.4e38f;
    for (int i = lane; i < cnt; i += 32)
        gmin = fminf(gmin, __uint_as_float(lst[i].x));
#pragma unroll
    for (int off = 16; off; off >>= 1)
        gmin = fminf(gmin, __shfl_xor_sync(0xFFFFFFFFu, gmin, off));
    const float thr = gmin + RESCORE_M;

    // exact fp32 rescore of finalists
    const float* zq = g_At + (size_t)q * Dd;
    unsigned long long best = 0xFFFFFFFFFFFFFFFFULL;
    for (int base = 0; base < cnt; base += 32) {
        int i = base + lane;
        uint2 e = (i < cnt) ? lst[i] : make_uint2(0x7F800000u, 0u);
        unsigned act = __ballot_sync(0xFFFFFFFFu, __uint_as_float(e.x) < thr);
        while (act) {
            int j = __ffs(act) - 1;
            act &= act - 1;
            int code = __shfl_sync(0xFFFFFFFFu, (int)e.y, j);
            const float* cr = cb + (size_t)code * Dd;
            float s = 0.0f;
#pragma unroll
            for (int d = 0; d < Dd / 32; d++)
                s = fmaf(zq[lane + d * 32], cr[lane + d * 32], s);
#pragma unroll
            for (int off = 16; off; off >>= 1)
                s += __shfl_down_sync(0xFFFFFFFFu, s, off);
            if (lane == 0) {
                float dex = g_c2[code] - 2.0f * s;
                unsigned long long pk =
                    ((unsigned long long)f_ord(dex) << 32) | (unsigned)code;
                best = min(best, pk);
            }
        }
    }
    best = __shfl_sync(0xFFFFFFFFu, best, 0);
    int idx = (int)(best & 0xFFFFFFFFULL);
    if (lane == 0) atomicAdd(&g_cnt[idx], 1);

    // stage chosen codebook row transposed: st[d][wid]
    const float* cr = cb + (size_t)idx * Dd;
#pragma unroll
    for (int k = 0; k < 16; k++)
        st[lane + 32 * k][wid] = cr[lane + 32 * k];
    __syncthreads();

    // coalesced (32B-sector) write of z_q tile + commitment loss
    const int b = (blockIdx.x * 8) >> 8;
    const int t0 = (blockIdx.x * 8) & 255;
    float ls = 0.0f;
#pragma unroll
    for (int p = 0; p < 2; p++) {
        int d = tid + 256 * p;
        size_t o = ((size_t)b * Dd + d) * Tt + t0;
        float4 z0 = *(const float4*)(z + o);
        float4 z1 = *(const float4*)(z + o + 4);
        float4 v0 = make_float4(st[d][0], st[d][1], st[d][2], st[d][3]);
        float4 v1 = make_float4(st[d][4], st[d][5], st[d][6], st[d][7]);
        *(float4*)(out + o)     = v0;
        *(float4*)(out + o + 4) = v1;
        float d0 = v0.x - z0.x, d1 = v0.y - z0.y, d2 = v0.z - z0.z, d3 = v0.w - z0.w;
        float d4 = v1.x - z1.x, d5 = v1.y - z1.y, d6 = v1.z - z1.z, d7 = v1.w - z1.w;
        ls += d0 * d0 + d1 * d1 + d2 * d2 + d3 * d3
            + d4 * d4 + d5 * d5 + d6 * d6 + d7 * d7;
    }
#pragma unroll
    for (int off = 16; off; off >>= 1) ls += __shfl_down_sync(0xFFFFFFFFu, ls, off);
    if (lane == 0) wls[wid] = ls;
    __syncthreads();
    if (tid == 0) {
        float tot = 0.0f;
#pragma unroll
        for (int i = 0; i < 8; i++) tot += wls[i];
        atomicAdd(&g_loss, tot);
    }
}

// 6: finalize loss + perplexity
__global__ void k_final(float* __restrict__ out) {
    int t = threadIdx.x;
    float local = 0.0f;
    for (int k = t; k < Kc; k += 256) {
        float p = (float)g_cnt[k] * (1.0f / (float)Nq);
        local += p * logf(p + 1e-10f);
    }
#pragma unroll
    for (int off = 16; off; off >>= 1) local += __shfl_down_sync(0xFFFFFFFFu, local, off);
    __shared__ float ws[8];
    if ((t & 31) == 0) ws[t >> 5] = local;
    __syncthreads();
    if (t == 0) {
        float tot = 0.0f;
#pragma unroll
        for (int i = 0; i < 8; i++) tot += ws[i];
        size_t base = (size_t)Bq * Dd * Tt;
        out[base]     = 0.25f * g_loss / (float)((size_t)Nq * Dd);
        out[base + 1] = expf(-tot);
    }
}

// ---------------------------------------------------------------------------
extern "C" void kernel_launch(void* const* d_in, const int* in_sizes, int n_in,
                              void* d_out, int out_size) {
    const float* z  = (const float*)d_in[0];
    const float* cb = (const float*)d_in[1];
    float* out = (float*)d_out;
    (void)in_sizes; (void)n_in; (void)out_size;

    cudaFuncSetAttribute(k_gemm, cudaFuncAttributeMaxDynamicSharedMemorySize,
                         STAGES * STG_BYTES);

    k_conv<<<512 + Kc / 2, 256>>>(z, cb);                               // 1
    k_zero1<<<Nq / 256, 256>>>();                                       // 2
    k_zero2<<<Kc / 256, 256>>>();                                       // 3
    k_gemm<<<dim3(Nq / BM, Kc / BN), NTHREADS, STAGES * STG_BYTES>>>(); // 4 (ncu)
    k_scanout<<<Nq / 8, 256>>>(z, cb, out);                             // 5
    k_final<<<1, 256>>>(out);                                           // 6
}